// round 4
// baseline (speedup 1.0000x reference)
#include <cuda_runtime.h>
#include <cuda_bf16.h>
#include <cstdint>

#define N_NODES 100000
#define N_EDGES 3200000
#define F_IN 256
#define CH 16
#define FCN 64

// Scratch: __device__ globals (no allocation allowed).
__device__ __align__(16) float g_h[N_NODES * CH];
__device__ __align__(16) float g_agg[N_NODES * CH];
__device__ __align__(16) int2  g_rec[N_EDGES];        // (src, w_bits) sorted by dst
__device__ int g_hist[N_NODES];
__device__ int g_ptr[N_NODES + 1];
__device__ int g_cursor[N_NODES];
__device__ int g_idx_is64;   // 1 if edge_index is int64, 0 if int32

// ---------------------------------------------------------------------------
// Kernel 0: zero histogram (all blocks) + probe edge_index dtype (block 0).
// int64 (nonneg < 2^31): every odd 32-bit word is zero.
// int32: odd words are random node ids -> some nonzero among 8192 w.p. ~1.
// ---------------------------------------------------------------------------
__global__ void k0_init(const int* __restrict__ ei32, int n_words) {
    int gid = blockIdx.x * blockDim.x + threadIdx.x;
    if (gid < N_NODES) g_hist[gid] = 0;

    if (blockIdx.x == 0) {
        __shared__ int any;
        if (threadIdx.x == 0) any = 0;
        __syncthreads();
        int limit = n_words < 8192 ? n_words : 8192;
        for (int i = 1 + 2 * threadIdx.x; i < limit; i += 2 * blockDim.x)
            if (ei32[i] != 0) any = 1;   // benign race: all writers store 1
        __syncthreads();
        if (threadIdx.x == 0) g_idx_is64 = (any == 0) ? 1 : 0;
    }
}

// ---------------------------------------------------------------------------
// Kernel 1: h = x @ w_gcn (warp per node), FUSED with dst histogram.
// Grid = exactly 3.2M threads: thread t also counts edge t's destination.
// The int REDs hide under this kernel's DRAM-bound 102MB x read.
// ---------------------------------------------------------------------------
__global__ void k1_xw_hist(const float* __restrict__ x,
                           const float* __restrict__ w_gcn,
                           const int* __restrict__ ei32, int E) {
    __shared__ float w_t[F_IN * CH];
    const int tid = threadIdx.x;
    for (int i = tid; i < F_IN * CH; i += blockDim.x) {
        int k = i >> 4;
        int c = i & 15;
        w_t[c * F_IN + k] = w_gcn[i];
    }
    __syncthreads();

    const int gtid = blockIdx.x * blockDim.x + tid;

    // Histogram of destinations (1 edge per thread; grid covers E exactly)
    if (gtid < E) {
        int dst = g_idx_is64 ? ei32[(size_t)2 * (E + gtid)] : ei32[(size_t)E + gtid];
        atomicAdd(&g_hist[dst], 1);   // no return -> RED
    }

    const int warp = gtid >> 5;
    const int lane = tid & 31;
    if (warp >= N_NODES) return;

    const float* __restrict__ xr = x + (size_t)warp * F_IN;
    float acc[CH];
#pragma unroll
    for (int c = 0; c < CH; c++) acc[c] = 0.0f;

#pragma unroll
    for (int i = 0; i < F_IN / 32; i++) {
        float xv = xr[i * 32 + lane];          // coalesced
#pragma unroll
        for (int c = 0; c < CH; c++)
            acc[c] += xv * w_t[c * F_IN + i * 32 + lane];  // conflict-free LDS
    }

    float mine = 0.0f;
#pragma unroll
    for (int c = 0; c < CH; c++) {
        float v = acc[c];
#pragma unroll
        for (int o = 16; o > 0; o >>= 1)
            v += __shfl_xor_sync(0xFFFFFFFFu, v, o);
        if (lane == c) mine = v;
    }
    if (lane < CH) g_h[(size_t)warp * CH + lane] = mine;
}

// ---------------------------------------------------------------------------
// Kernel 2b: exclusive scan of g_hist -> g_ptr / g_cursor. One block, 1024 thr.
// Each thread owns CHUNK=98 consecutive counters (1024*98 >= 100000).
// Pass 1: per-thread sum. Block Hillis-Steele scan. Pass 2: write prefixes.
// ---------------------------------------------------------------------------
__global__ void k2b_scan() {
    const int CHUNK = 98;
    __shared__ int s[1024];
    int t = threadIdx.x;
    int base = t * CHUNK;

    int sum = 0;
    for (int i = 0; i < CHUNK; i++) {
        int idx = base + i;
        if (idx < N_NODES) sum += g_hist[idx];
    }
    s[t] = sum;
    __syncthreads();

    // Inclusive scan over 1024 partial sums
    for (int off = 1; off < 1024; off <<= 1) {
        int v = (t >= off) ? s[t - off] : 0;
        __syncthreads();
        s[t] += v;
        __syncthreads();
    }

    int run = (t > 0) ? s[t - 1] : 0;   // exclusive prefix for this chunk
    for (int i = 0; i < CHUNK; i++) {
        int idx = base + i;
        if (idx < N_NODES) {
            g_ptr[idx] = run;
            g_cursor[idx] = run;
            run += g_hist[idx];
        }
    }
    if (t == 1023) g_ptr[N_NODES] = run;   // == E
}

// ---------------------------------------------------------------------------
// Kernel 2c: scatter edges into dst-sorted record array.
// One thread per edge: p = cursor[dst]++; rec[p] = (src, w).
// ---------------------------------------------------------------------------
__global__ void k2c_scatter(const int* __restrict__ ei32,
                            const float* __restrict__ ew, int E) {
    int e = blockIdx.x * blockDim.x + threadIdx.x;
    if (e >= E) return;

    int src, dst;
    if (g_idx_is64) {
        src = ei32[(size_t)2 * e];
        dst = ei32[(size_t)2 * (E + e)];
    } else {
        src = ei32[e];
        dst = ei32[(size_t)E + e];
    }
    float w = ew[e];

    int p = atomicAdd(&g_cursor[dst], 1);
    g_rec[p] = make_int2(src, __float_as_int(w));
}

// ---------------------------------------------------------------------------
// Kernel 2d: atomic-free aggregation. One warp per node.
// Edges processed 8 per iteration: lanes 0-7 load 8 records (coalesced),
// broadcast via shfl; 4 lanes per edge gather a 64B h-row (coalesced),
// scale, accumulate in registers. Butterfly over edge-slots, lanes 0-3
// write the node's 64B agg row.
// ---------------------------------------------------------------------------
__global__ void k2d_agg() {
    const unsigned FULL = 0xFFFFFFFFu;
    int gtid = blockIdx.x * blockDim.x + threadIdx.x;
    int n = gtid >> 5;
    if (n >= N_NODES) return;
    int lane = threadIdx.x & 31;
    int slot = lane >> 2;     // 0..7 : which of 8 edges in the batch
    int j = lane & 3;         // 0..3 : which float4 of the 16-ch row

    int start = g_ptr[n];
    int end = g_ptr[n + 1];

    float ax = 0.f, ay = 0.f, az = 0.f, aw = 0.f;

    for (int base = start; base < end; base += 8) {
        int2 r = make_int2(0, 0);              // src=0, w=0 padding
        if (lane < 8) {
            int idx = base + lane;
            if (idx < end) r = g_rec[idx];
        }
        int src = __shfl_sync(FULL, r.x, slot);
        float w = __int_as_float(__shfl_sync(FULL, r.y, slot));

        const float4 hv = *(const float4*)(g_h + (size_t)src * CH + j * 4);
        ax += hv.x * w; ay += hv.y * w; az += hv.z * w; aw += hv.w * w;
    }

    // Reduce across the 8 edge-slots (lane bits 2..4)
#pragma unroll
    for (int m = 4; m <= 16; m <<= 1) {
        ax += __shfl_xor_sync(FULL, ax, m);
        ay += __shfl_xor_sync(FULL, ay, m);
        az += __shfl_xor_sync(FULL, az, m);
        aw += __shfl_xor_sync(FULL, aw, m);
    }

    if (lane < 4)
        *(float4*)(g_agg + (size_t)n * CH + lane * 4) = make_float4(ax, ay, az, aw);
}

// ---------------------------------------------------------------------------
// Kernel 3: per-node FCN head. w0 transposed [f][c] in smem, LDS.128 reads.
// ---------------------------------------------------------------------------
__global__ void k3_head(const float* __restrict__ w0, const float* __restrict__ b0,
                        const float* __restrict__ w1, const float* __restrict__ b1,
                        float* __restrict__ out) {
    __shared__ float s_w0t[FCN * CH];   // [f][c]
    __shared__ float s_w1[FCN];
    __shared__ float s_b0[FCN];
    __shared__ float s_b1;
    const int tid = threadIdx.x;
    for (int i = tid; i < CH * FCN; i += blockDim.x) {
        int c = i / FCN, f = i % FCN;
        s_w0t[f * CH + c] = w0[i];
    }
    for (int i = tid; i < FCN; i += blockDim.x) { s_w1[i] = w1[i]; s_b0[i] = b0[i]; }
    if (tid == 0) s_b1 = b1[0];
    __syncthreads();

    const int n = blockIdx.x * blockDim.x + tid;
    if (n >= N_NODES) return;

    float4 a4[4];
    const float4* ap = (const float4*)(g_agg + (size_t)n * CH);
#pragma unroll
    for (int q = 0; q < 4; q++) {
        float4 v = ap[q];
        a4[q].x = fmaxf(v.x, 0.f); a4[q].y = fmaxf(v.y, 0.f);
        a4[q].z = fmaxf(v.z, 0.f); a4[q].w = fmaxf(v.w, 0.f);
    }

    const float4* w0t4 = (const float4*)s_w0t;  // [f][c/4]
    float o2 = s_b1;
#pragma unroll 4
    for (int f = 0; f < FCN; f++) {
        float o1 = s_b0[f];
#pragma unroll
        for (int q = 0; q < 4; q++) {
            float4 w4 = w0t4[f * 4 + q];        // LDS.128, broadcast
            o1 += a4[q].x * w4.x + a4[q].y * w4.y
                + a4[q].z * w4.z + a4[q].w * w4.w;
        }
        o1 = fmaxf(o1, 0.0f);
        o2 += o1 * s_w1[f];
    }
    out[n] = o2;
}

// ---------------------------------------------------------------------------
// Launcher. Inputs identified by element count (robust to ordering):
//   x: 25,600,000   edge_index: 6,400,000   edge_w: 3,200,000
//   w_gcn: 4096     w0: 1024   b0: 64 (first)   w1: 64 (second)   b1: 1
// ---------------------------------------------------------------------------
extern "C" void kernel_launch(void* const* d_in, const int* in_sizes, int n_in,
                              void* d_out, int out_size) {
    const float* x = nullptr;
    const int* ei = nullptr;
    const float* ew = nullptr;
    const float* wg = nullptr;
    const float* w0 = nullptr;
    const float* b0 = nullptr;
    const float* w1 = nullptr;
    const float* b1 = nullptr;
    int E = 0;
    int seen64 = 0;

    for (int i = 0; i < n_in; i++) {
        int s = in_sizes[i];
        if (s == N_NODES * F_IN)      x  = (const float*)d_in[i];
        else if (s == 2 * N_EDGES)    { ei = (const int*)d_in[i]; E = s / 2; }
        else if (s == N_EDGES)        ew = (const float*)d_in[i];
        else if (s == F_IN * CH)      wg = (const float*)d_in[i];
        else if (s == CH * FCN)       w0 = (const float*)d_in[i];
        else if (s == FCN)            { if (seen64++ == 0) b0 = (const float*)d_in[i];
                                        else               w1 = (const float*)d_in[i]; }
        else if (s == 1)              b1 = (const float*)d_in[i];
    }

    float* out = (float*)d_out;

    // K0: zero hist + dtype probe
    k0_init<<<(N_NODES + 255) / 256, 256>>>(ei, 2 * E);

    // K1: warp per node GEMV, fused dst histogram (grid = 3.2M threads = E)
    k1_xw_hist<<<(N_NODES * 32) / 256, 256>>>(x, wg, ei, E);

    // K2b: exclusive scan (single block)
    k2b_scan<<<1, 1024>>>();

    // K2c: scatter into CSR records
    k2c_scatter<<<(E + 255) / 256, 256>>>(ei, ew, E);

    // K2d: atomic-free aggregation, warp per node
    k2d_agg<<<(N_NODES * 32 + 255) / 256, 256>>>();

    // K3: thread per node FCN head
    k3_head<<<(N_NODES + 127) / 128, 128>>>(w0, b0, w1, b1, out);
}

// round 5
// speedup vs baseline: 1.5718x; 1.5718x over previous
#include <cuda_runtime.h>
#include <cuda_bf16.h>
#include <cstdint>

#define N_NODES 100000
#define N_EDGES 3200000
#define F_IN 256
#define CH 16
#define FCN 64

#define SCAN_B 1024
#define SCAN_NB ((N_NODES + SCAN_B - 1) / SCAN_B)   // 98

// Scratch: __device__ globals (no allocation allowed).
__device__ __align__(16) float g_h[N_NODES * CH];
__device__ __align__(16) float g_agg[N_NODES * CH];
__device__ __align__(16) int2  g_rec[N_EDGES];        // (src, w_bits) sorted by dst
__device__ int g_hist[N_NODES];
__device__ int g_ptr[N_NODES + 1];
__device__ int g_cursor[N_NODES];
__device__ int g_bsum[SCAN_NB];
__device__ int g_boff[SCAN_NB];
__device__ int g_idx_is64;   // 1 if edge_index is int64, 0 if int32

// ---------------------------------------------------------------------------
// Kernel 0: zero histogram (all blocks) + probe edge_index dtype (block 0).
// int64 (nonneg < 2^31): every odd 32-bit word is zero.
// int32: odd words are random node ids -> some nonzero among 8192 w.p. ~1.
// ---------------------------------------------------------------------------
__global__ void k0_init(const int* __restrict__ ei32, int n_words) {
    int gid = blockIdx.x * blockDim.x + threadIdx.x;
    if (gid < N_NODES) g_hist[gid] = 0;

    if (blockIdx.x == 0) {
        __shared__ int any;
        if (threadIdx.x == 0) any = 0;
        __syncthreads();
        int limit = n_words < 8192 ? n_words : 8192;
        for (int i = 1 + 2 * threadIdx.x; i < limit; i += 2 * blockDim.x)
            if (ei32[i] != 0) any = 1;   // benign race: all writers store 1
        __syncthreads();
        if (threadIdx.x == 0) g_idx_is64 = (any == 0) ? 1 : 0;
    }
}

// ---------------------------------------------------------------------------
// Kernel 1: h = x @ w_gcn (warp per node), FUSED with dst histogram.
// Grid = exactly 3.2M threads: thread t also counts edge t's destination.
// The int REDs hide under this kernel's DRAM-bound 102MB x read.
// ---------------------------------------------------------------------------
__global__ void k1_xw_hist(const float* __restrict__ x,
                           const float* __restrict__ w_gcn,
                           const int* __restrict__ ei32, int E) {
    __shared__ float w_t[F_IN * CH];
    const int tid = threadIdx.x;
    for (int i = tid; i < F_IN * CH; i += blockDim.x) {
        int k = i >> 4;
        int c = i & 15;
        w_t[c * F_IN + k] = w_gcn[i];
    }
    __syncthreads();

    const int gtid = blockIdx.x * blockDim.x + tid;

    // Histogram of destinations (1 edge per thread; grid covers E exactly)
    if (gtid < E) {
        int dst = g_idx_is64 ? ei32[(size_t)2 * (E + gtid)] : ei32[(size_t)E + gtid];
        atomicAdd(&g_hist[dst], 1);   // no return -> RED
    }

    const int warp = gtid >> 5;
    const int lane = tid & 31;
    if (warp >= N_NODES) return;

    const float* __restrict__ xr = x + (size_t)warp * F_IN;
    float acc[CH];
#pragma unroll
    for (int c = 0; c < CH; c++) acc[c] = 0.0f;

#pragma unroll
    for (int i = 0; i < F_IN / 32; i++) {
        float xv = xr[i * 32 + lane];          // coalesced
#pragma unroll
        for (int c = 0; c < CH; c++)
            acc[c] += xv * w_t[c * F_IN + i * 32 + lane];  // conflict-free LDS
    }

    float mine = 0.0f;
#pragma unroll
    for (int c = 0; c < CH; c++) {
        float v = acc[c];
#pragma unroll
        for (int o = 16; o > 0; o >>= 1)
            v += __shfl_xor_sync(0xFFFFFFFFu, v, o);
        if (lane == c) mine = v;
    }
    if (lane < CH) g_h[(size_t)warp * CH + lane] = mine;
}

// ---------------------------------------------------------------------------
// Scan phase A: per-block inclusive scan of 1024 counters (coalesced).
// Writes local EXCLUSIVE prefix into g_ptr and the block total to g_bsum.
// ---------------------------------------------------------------------------
__global__ void k2a_scan_local() {
    __shared__ int s[SCAN_B];
    int t = threadIdx.x;
    int idx = blockIdx.x * SCAN_B + t;
    int v = (idx < N_NODES) ? g_hist[idx] : 0;
    s[t] = v;
    __syncthreads();
#pragma unroll
    for (int off = 1; off < SCAN_B; off <<= 1) {
        int u = (t >= off) ? s[t - off] : 0;
        __syncthreads();
        s[t] += u;
        __syncthreads();
    }
    if (idx < N_NODES) g_ptr[idx] = s[t] - v;       // local exclusive
    if (t == SCAN_B - 1) g_bsum[blockIdx.x] = s[t]; // block total
}

// ---------------------------------------------------------------------------
// Scan phase B: one small block scans the 98 block totals (exclusive).
// ---------------------------------------------------------------------------
__global__ void k2b_scan_blocks() {
    __shared__ int s[128];
    int t = threadIdx.x;
    int v = (t < SCAN_NB) ? g_bsum[t] : 0;
    s[t] = v;
    __syncthreads();
#pragma unroll
    for (int off = 1; off < 128; off <<= 1) {
        int u = (t >= off) ? s[t - off] : 0;
        __syncthreads();
        s[t] += u;
        __syncthreads();
    }
    if (t < SCAN_NB) g_boff[t] = s[t] - v;          // exclusive block offset
    if (t == 127) g_ptr[N_NODES] = s[t];            // == E
}

// ---------------------------------------------------------------------------
// Scan phase C: add block offsets; init cursors. Coalesced.
// ---------------------------------------------------------------------------
__global__ void k2c_scan_apply() {
    int idx = blockIdx.x * SCAN_B + threadIdx.x;
    if (idx < N_NODES) {
        int p = g_ptr[idx] + g_boff[blockIdx.x];
        g_ptr[idx] = p;
        g_cursor[idx] = p;
    }
}

// ---------------------------------------------------------------------------
// Kernel 2c: scatter edges into dst-sorted record array.
// One thread per edge: p = cursor[dst]++; rec[p] = (src, w).
// ---------------------------------------------------------------------------
__global__ void k2c_scatter(const int* __restrict__ ei32,
                            const float* __restrict__ ew, int E) {
    int e = blockIdx.x * blockDim.x + threadIdx.x;
    if (e >= E) return;

    int src, dst;
    if (g_idx_is64) {
        src = ei32[(size_t)2 * e];
        dst = ei32[(size_t)2 * (E + e)];
    } else {
        src = ei32[e];
        dst = ei32[(size_t)E + e];
    }
    float w = ew[e];

    int p = atomicAdd(&g_cursor[dst], 1);
    g_rec[p] = make_int2(src, __float_as_int(w));
}

// ---------------------------------------------------------------------------
// Kernel 2d: atomic-free aggregation. One warp per node.
// 32 records loaded per iteration (coalesced 256B), consumed in 4 groups
// of 8 edges; 4 lanes per edge gather a 64B h-row (coalesced), scale,
// accumulate in registers. Butterfly over edge-slots, lanes 0-3 store.
// ---------------------------------------------------------------------------
__global__ void k2d_agg() {
    const unsigned FULL = 0xFFFFFFFFu;
    int gtid = blockIdx.x * blockDim.x + threadIdx.x;
    int n = gtid >> 5;
    if (n >= N_NODES) return;
    int lane = threadIdx.x & 31;
    int slot = lane >> 2;     // 0..7 : edge within a group of 8
    int j = lane & 3;         // 0..3 : which float4 of the 16-ch row

    int start = g_ptr[n];
    int end = g_ptr[n + 1];

    float ax = 0.f, ay = 0.f, az = 0.f, aw = 0.f;

    for (int base = start; base < end; base += 32) {
        int2 r = make_int2(0, 0);              // src=0, w=0 padding
        int idx = base + lane;
        if (idx < end) r = g_rec[idx];         // coalesced 256B

#pragma unroll
        for (int g = 0; g < 4; g++) {
            if (base + g * 8 >= end) break;
            int src = __shfl_sync(FULL, r.x, g * 8 + slot);
            float w = __int_as_float(__shfl_sync(FULL, r.y, g * 8 + slot));
            const float4 hv = *(const float4*)(g_h + (size_t)src * CH + j * 4);
            ax += hv.x * w; ay += hv.y * w; az += hv.z * w; aw += hv.w * w;
        }
    }

    // Reduce across the 8 edge-slots (lane bits 2..4)
#pragma unroll
    for (int m = 4; m <= 16; m <<= 1) {
        ax += __shfl_xor_sync(FULL, ax, m);
        ay += __shfl_xor_sync(FULL, ay, m);
        az += __shfl_xor_sync(FULL, az, m);
        aw += __shfl_xor_sync(FULL, aw, m);
    }

    if (lane < 4)
        *(float4*)(g_agg + (size_t)n * CH + lane * 4) = make_float4(ax, ay, az, aw);
}

// ---------------------------------------------------------------------------
// Kernel 3: per-node FCN head. w0 transposed [f][c] in smem, LDS.128 reads.
// ---------------------------------------------------------------------------
__global__ void k3_head(const float* __restrict__ w0, const float* __restrict__ b0,
                        const float* __restrict__ w1, const float* __restrict__ b1,
                        float* __restrict__ out) {
    __shared__ float s_w0t[FCN * CH];   // [f][c]
    __shared__ float s_w1[FCN];
    __shared__ float s_b0[FCN];
    __shared__ float s_b1;
    const int tid = threadIdx.x;
    for (int i = tid; i < CH * FCN; i += blockDim.x) {
        int c = i / FCN, f = i % FCN;
        s_w0t[f * CH + c] = w0[i];
    }
    for (int i = tid; i < FCN; i += blockDim.x) { s_w1[i] = w1[i]; s_b0[i] = b0[i]; }
    if (tid == 0) s_b1 = b1[0];
    __syncthreads();

    const int n = blockIdx.x * blockDim.x + tid;
    if (n >= N_NODES) return;

    float4 a4[4];
    const float4* ap = (const float4*)(g_agg + (size_t)n * CH);
#pragma unroll
    for (int q = 0; q < 4; q++) {
        float4 v = ap[q];
        a4[q].x = fmaxf(v.x, 0.f); a4[q].y = fmaxf(v.y, 0.f);
        a4[q].z = fmaxf(v.z, 0.f); a4[q].w = fmaxf(v.w, 0.f);
    }

    const float4* w0t4 = (const float4*)s_w0t;  // [f][c/4]
    float o2 = s_b1;
#pragma unroll 4
    for (int f = 0; f < FCN; f++) {
        float o1 = s_b0[f];
#pragma unroll
        for (int q = 0; q < 4; q++) {
            float4 w4 = w0t4[f * 4 + q];        // LDS.128, broadcast
            o1 += a4[q].x * w4.x + a4[q].y * w4.y
                + a4[q].z * w4.z + a4[q].w * w4.w;
        }
        o1 = fmaxf(o1, 0.0f);
        o2 += o1 * s_w1[f];
    }
    out[n] = o2;
}

// ---------------------------------------------------------------------------
// Launcher. Inputs identified by element count (robust to ordering):
//   x: 25,600,000   edge_index: 6,400,000   edge_w: 3,200,000
//   w_gcn: 4096     w0: 1024   b0: 64 (first)   w1: 64 (second)   b1: 1
// ---------------------------------------------------------------------------
extern "C" void kernel_launch(void* const* d_in, const int* in_sizes, int n_in,
                              void* d_out, int out_size) {
    const float* x = nullptr;
    const int* ei = nullptr;
    const float* ew = nullptr;
    const float* wg = nullptr;
    const float* w0 = nullptr;
    const float* b0 = nullptr;
    const float* w1 = nullptr;
    const float* b1 = nullptr;
    int E = 0;
    int seen64 = 0;

    for (int i = 0; i < n_in; i++) {
        int s = in_sizes[i];
        if (s == N_NODES * F_IN)      x  = (const float*)d_in[i];
        else if (s == 2 * N_EDGES)    { ei = (const int*)d_in[i]; E = s / 2; }
        else if (s == N_EDGES)        ew = (const float*)d_in[i];
        else if (s == F_IN * CH)      wg = (const float*)d_in[i];
        else if (s == CH * FCN)       w0 = (const float*)d_in[i];
        else if (s == FCN)            { if (seen64++ == 0) b0 = (const float*)d_in[i];
                                        else               w1 = (const float*)d_in[i]; }
        else if (s == 1)              b1 = (const float*)d_in[i];
    }

    float* out = (float*)d_out;

    // K0: zero hist + dtype probe
    k0_init<<<(N_NODES + 255) / 256, 256>>>(ei, 2 * E);

    // K1: warp per node GEMV, fused dst histogram (grid = 3.2M threads = E)
    k1_xw_hist<<<(N_NODES * 32) / 256, 256>>>(x, wg, ei, E);

    // Scan: 3 coalesced phases
    k2a_scan_local<<<SCAN_NB, SCAN_B>>>();
    k2b_scan_blocks<<<1, 128>>>();
    k2c_scan_apply<<<SCAN_NB, SCAN_B>>>();

    // K2c: scatter into CSR records
    k2c_scatter<<<(E + 255) / 256, 256>>>(ei, ew, E);

    // K2d: atomic-free aggregation, warp per node
    k2d_agg<<<(N_NODES * 32 + 255) / 256, 256>>>();

    // K3: thread per node FCN head
    k3_head<<<(N_NODES + 127) / 128, 128>>>(w0, b0, w1, b1, out);
}

// round 6
// speedup vs baseline: 2.0480x; 1.3030x over previous
#include <cuda_runtime.h>
#include <cuda_bf16.h>
#include <cstdint>

#define N_NODES 100000
#define N_EDGES 3200000
#define F_IN 256
#define CH 16
#define FCN 64

#define SCAN_B 1024
#define SCAN_NB ((N_NODES + SCAN_B - 1) / SCAN_B)   // 98

// Scratch: __device__ globals (no allocation allowed).
__device__ __align__(16) float g_h[N_NODES * CH];
__device__ __align__(16) int2  g_rec[N_EDGES];        // (src, w_bits) grouped by dst
__device__ int g_hist[N_NODES];
__device__ int g_ptr[N_NODES + 1];
__device__ int g_cursor[N_NODES];
__device__ int g_bsum[SCAN_NB];
__device__ int g_boff[SCAN_NB];
__device__ int g_idx_is64;   // 1 if edge_index is int64, 0 if int32

// ---------------------------------------------------------------------------
// Kernel 0: zero histogram (all blocks) + probe edge_index dtype (block 0).
// int64 (nonneg < 2^31): every odd 32-bit word is zero.
// int32: odd words are random node ids -> some nonzero among 8192 w.p. ~1.
// ---------------------------------------------------------------------------
__global__ void k0_init(const int* __restrict__ ei32, int n_words) {
    int gid = blockIdx.x * blockDim.x + threadIdx.x;
    if (gid < N_NODES) g_hist[gid] = 0;

    if (blockIdx.x == 0) {
        __shared__ int any;
        if (threadIdx.x == 0) any = 0;
        __syncthreads();
        int limit = n_words < 8192 ? n_words : 8192;
        for (int i = 1 + 2 * threadIdx.x; i < limit; i += 2 * blockDim.x)
            if (ei32[i] != 0) any = 1;   // benign race: all writers store 1
        __syncthreads();
        if (threadIdx.x == 0) g_idx_is64 = (any == 0) ? 1 : 0;
    }
}

// ---------------------------------------------------------------------------
// Kernel 1: h = x @ w_gcn. FOUR nodes per warp: each w_t LDS value feeds
// 4 FFMAs -> smem crossbar cost per node drops 4x vs one-node-per-warp.
// Also fused: dst histogram (strided loop over edges).
// ---------------------------------------------------------------------------
__global__ void k1_xw_hist(const float* __restrict__ x,
                           const float* __restrict__ w_gcn,
                           const int* __restrict__ ei32, int E) {
    __shared__ float w_t[F_IN * CH];    // [c][k], pitch 256: lane-consecutive
    const int tid = threadIdx.x;
    for (int i = tid; i < F_IN * CH; i += blockDim.x) {
        int k = i >> 4;
        int c = i & 15;
        w_t[c * F_IN + k] = w_gcn[i];
    }
    __syncthreads();

    const int gtid = blockIdx.x * blockDim.x + tid;
    const int nthreads = gridDim.x * blockDim.x;

    // Histogram of destinations (strided; REDs hide under the DRAM-bound x read)
    const int is64 = g_idx_is64;
    for (int e = gtid; e < E; e += nthreads) {
        int dst = is64 ? ei32[(size_t)2 * (E + e)] : ei32[(size_t)E + e];
        atomicAdd(&g_hist[dst], 1);   // no return -> RED
    }

    const int warp = gtid >> 5;
    const int lane = tid & 31;
    const int n0 = warp * 4;
    if (n0 >= N_NODES) return;       // N_NODES % 4 == 0

    const float* __restrict__ xr = x + (size_t)n0 * F_IN;
    float acc0[CH], acc1[CH], acc2[CH], acc3[CH];
#pragma unroll
    for (int c = 0; c < CH; c++) { acc0[c] = acc1[c] = acc2[c] = acc3[c] = 0.f; }

#pragma unroll
    for (int i = 0; i < F_IN / 32; i++) {
        int k = i * 32 + lane;
        float xa = xr[k];                    // coalesced, 4 rows
        float xb = xr[F_IN + k];
        float xc = xr[2 * F_IN + k];
        float xd = xr[3 * F_IN + k];
#pragma unroll
        for (int c = 0; c < CH; c++) {
            float wv = w_t[c * F_IN + k];    // 1 LDS feeds 4 FFMA
            acc0[c] += xa * wv;
            acc1[c] += xb * wv;
            acc2[c] += xc * wv;
            acc3[c] += xd * wv;
        }
    }

    // Butterfly-reduce each (node, channel); lane c stores channel c.
#pragma unroll
    for (int m = 0; m < 4; m++) {
        float* acc = (m == 0) ? acc0 : (m == 1) ? acc1 : (m == 2) ? acc2 : acc3;
        float mine = 0.0f;
#pragma unroll
        for (int c = 0; c < CH; c++) {
            float v = acc[c];
#pragma unroll
            for (int o = 16; o > 0; o >>= 1)
                v += __shfl_xor_sync(0xFFFFFFFFu, v, o);
            if (lane == c) mine = v;
        }
        if (lane < CH) g_h[(size_t)(n0 + m) * CH + lane] = mine;
    }
}

// ---------------------------------------------------------------------------
// Scan phase A: per-block inclusive scan of 1024 counters (coalesced).
// ---------------------------------------------------------------------------
__global__ void k2a_scan_local() {
    __shared__ int s[SCAN_B];
    int t = threadIdx.x;
    int idx = blockIdx.x * SCAN_B + t;
    int v = (idx < N_NODES) ? g_hist[idx] : 0;
    s[t] = v;
    __syncthreads();
#pragma unroll
    for (int off = 1; off < SCAN_B; off <<= 1) {
        int u = (t >= off) ? s[t - off] : 0;
        __syncthreads();
        s[t] += u;
        __syncthreads();
    }
    if (idx < N_NODES) g_ptr[idx] = s[t] - v;       // local exclusive
    if (t == SCAN_B - 1) g_bsum[blockIdx.x] = s[t]; // block total
}

// ---------------------------------------------------------------------------
// Scan phase B: one small block scans the 98 block totals (exclusive).
// ---------------------------------------------------------------------------
__global__ void k2b_scan_blocks() {
    __shared__ int s[128];
    int t = threadIdx.x;
    int v = (t < SCAN_NB) ? g_bsum[t] : 0;
    s[t] = v;
    __syncthreads();
#pragma unroll
    for (int off = 1; off < 128; off <<= 1) {
        int u = (t >= off) ? s[t - off] : 0;
        __syncthreads();
        s[t] += u;
        __syncthreads();
    }
    if (t < SCAN_NB) g_boff[t] = s[t] - v;          // exclusive block offset
    if (t == 127) g_ptr[N_NODES] = s[t];            // == E
}

// ---------------------------------------------------------------------------
// Scan phase C: add block offsets; init cursors. Coalesced.
// ---------------------------------------------------------------------------
__global__ void k2c_scan_apply() {
    int idx = blockIdx.x * SCAN_B + threadIdx.x;
    if (idx < N_NODES) {
        int p = g_ptr[idx] + g_boff[blockIdx.x];
        g_ptr[idx] = p;
        g_cursor[idx] = p;
    }
}

// ---------------------------------------------------------------------------
// Kernel 2c: scatter edges into dst-grouped record array.
// ---------------------------------------------------------------------------
__global__ void k2c_scatter(const int* __restrict__ ei32,
                            const float* __restrict__ ew, int E) {
    int e = blockIdx.x * blockDim.x + threadIdx.x;
    if (e >= E) return;

    int src, dst;
    if (g_idx_is64) {
        src = ei32[(size_t)2 * e];
        dst = ei32[(size_t)2 * (E + e)];
    } else {
        src = ei32[e];
        dst = ei32[(size_t)E + e];
    }
    float w = ew[e];

    int p = atomicAdd(&g_cursor[dst], 1);
    g_rec[p] = make_int2(src, __float_as_int(w));
}

// ---------------------------------------------------------------------------
// Kernel 2d: atomic-free aggregation FUSED with FCN head. One warp per node.
// Edge loop: 32 records per coalesced load, 4 groups of 8 edges, 4 lanes per
// edge gather a 64B h-row. Butterfly -> lanes 0-3 hold the 16 channels.
// Head: broadcast channels via shfl; lane l computes FCN units l and l+32;
// final warp-reduce gives out[n]. No g_agg traffic, no separate k3 launch.
// ---------------------------------------------------------------------------
__global__ void k2d_agg_head(const float* __restrict__ w0, const float* __restrict__ b0,
                             const float* __restrict__ w1, const float* __restrict__ b1,
                             float* __restrict__ out) {
    __shared__ float s_w0[CH * FCN];    // [c][f]: lane-consecutive reads
    __shared__ float s_w1[FCN];
    __shared__ float s_b0[FCN];
    __shared__ float s_b1;
    const int tid = threadIdx.x;
    for (int i = tid; i < CH * FCN; i += blockDim.x) s_w0[i] = w0[i];
    for (int i = tid; i < FCN; i += blockDim.x) { s_w1[i] = w1[i]; s_b0[i] = b0[i]; }
    if (tid == 0) s_b1 = b1[0];
    __syncthreads();

    const unsigned FULL = 0xFFFFFFFFu;
    int gtid = blockIdx.x * blockDim.x + tid;
    int n = gtid >> 5;
    if (n >= N_NODES) return;
    int lane = tid & 31;
    int slot = lane >> 2;     // 0..7 : edge within a group of 8
    int j = lane & 3;         // 0..3 : which float4 of the 16-ch row

    int start = g_ptr[n];
    int end = g_ptr[n + 1];

    float ax = 0.f, ay = 0.f, az = 0.f, aw = 0.f;

    for (int base = start; base < end; base += 32) {
        int2 r = make_int2(0, 0);              // src=0, w=0 padding
        int idx = base + lane;
        if (idx < end) r = g_rec[idx];         // coalesced 256B

#pragma unroll
        for (int g = 0; g < 4; g++) {
            if (base + g * 8 >= end) break;
            int src = __shfl_sync(FULL, r.x, g * 8 + slot);
            float w = __int_as_float(__shfl_sync(FULL, r.y, g * 8 + slot));
            const float4 hv = *(const float4*)(g_h + (size_t)src * CH + j * 4);
            ax += hv.x * w; ay += hv.y * w; az += hv.z * w; aw += hv.w * w;
        }
    }

    // Reduce across the 8 edge-slots (lane bits 2..4): lanes 0-3 hold result
#pragma unroll
    for (int m = 4; m <= 16; m <<= 1) {
        ax += __shfl_xor_sync(FULL, ax, m);
        ay += __shfl_xor_sync(FULL, ay, m);
        az += __shfl_xor_sync(FULL, az, m);
        aw += __shfl_xor_sync(FULL, aw, m);
    }

    // Broadcast the 16 channels (relu'd) to all lanes: a[c], c = 4q+{0..3}
    float a[CH];
#pragma unroll
    for (int q = 0; q < 4; q++) {
        a[4 * q + 0] = fmaxf(__shfl_sync(FULL, ax, q), 0.f);
        a[4 * q + 1] = fmaxf(__shfl_sync(FULL, ay, q), 0.f);
        a[4 * q + 2] = fmaxf(__shfl_sync(FULL, az, q), 0.f);
        a[4 * q + 3] = fmaxf(__shfl_sync(FULL, aw, q), 0.f);
    }

    // FCN head: lane l computes units f=l and f=l+32.
    float o1a = s_b0[lane];
    float o1b = s_b0[lane + 32];
#pragma unroll
    for (int c = 0; c < CH; c++) {
        o1a += a[c] * s_w0[c * FCN + lane];        // conflict-free LDS
        o1b += a[c] * s_w0[c * FCN + lane + 32];
    }
    o1a = fmaxf(o1a, 0.f);
    o1b = fmaxf(o1b, 0.f);
    float o2 = o1a * s_w1[lane] + o1b * s_w1[lane + 32];
#pragma unroll
    for (int m = 16; m > 0; m >>= 1)
        o2 += __shfl_xor_sync(FULL, o2, m);
    if (lane == 0) out[n] = o2 + s_b1;
}

// ---------------------------------------------------------------------------
// Launcher. Inputs identified by element count (robust to ordering):
//   x: 25,600,000   edge_index: 6,400,000   edge_w: 3,200,000
//   w_gcn: 4096     w0: 1024   b0: 64 (first)   w1: 64 (second)   b1: 1
// ---------------------------------------------------------------------------
extern "C" void kernel_launch(void* const* d_in, const int* in_sizes, int n_in,
                              void* d_out, int out_size) {
    const float* x = nullptr;
    const int* ei = nullptr;
    const float* ew = nullptr;
    const float* wg = nullptr;
    const float* w0 = nullptr;
    const float* b0 = nullptr;
    const float* w1 = nullptr;
    const float* b1 = nullptr;
    int E = 0;
    int seen64 = 0;

    for (int i = 0; i < n_in; i++) {
        int s = in_sizes[i];
        if (s == N_NODES * F_IN)      x  = (const float*)d_in[i];
        else if (s == 2 * N_EDGES)    { ei = (const int*)d_in[i]; E = s / 2; }
        else if (s == N_EDGES)        ew = (const float*)d_in[i];
        else if (s == F_IN * CH)      wg = (const float*)d_in[i];
        else if (s == CH * FCN)       w0 = (const float*)d_in[i];
        else if (s == FCN)            { if (seen64++ == 0) b0 = (const float*)d_in[i];
                                        else               w1 = (const float*)d_in[i]; }
        else if (s == 1)              b1 = (const float*)d_in[i];
    }

    float* out = (float*)d_out;

    // K0: zero hist + dtype probe
    k0_init<<<(N_NODES + 255) / 256, 256>>>(ei, 2 * E);

    // K1: 4 nodes per warp GEMV + fused dst histogram
    {
        int warps = N_NODES / 4;                 // 25000
        int threads = 256;
        int blocks = (warps * 32 + threads - 1) / threads;  // 3125
        k1_xw_hist<<<blocks, threads>>>(x, wg, ei, E);
    }

    // Scan: 3 coalesced phases
    k2a_scan_local<<<SCAN_NB, SCAN_B>>>();
    k2b_scan_blocks<<<1, 128>>>();
    k2c_scan_apply<<<SCAN_NB, SCAN_B>>>();

    // K2c: scatter into CSR records
    k2c_scatter<<<(E + 255) / 256, 256>>>(ei, ew, E);

    // K2d: atomic-free aggregation + FCN head, warp per node
    k2d_agg_head<<<(N_NODES * 32 + 255) / 256, 256>>>(w0, b0, w1, b1, out);
}

// round 7
// speedup vs baseline: 2.0647x; 1.0082x over previous
#include <cuda_runtime.h>
#include <cuda_bf16.h>
#include <cstdint>

#define N_NODES 100000
#define N_EDGES 3200000
#define F_IN 256
#define CH 16
#define FCN 64

#define SCAN_B 1024
#define SCAN_NB ((N_NODES + SCAN_B - 1) / SCAN_B)   // 98
#define READY_BIT 0x40000000

// Scratch: __device__ globals (no allocation allowed).
__device__ __align__(128) float g_h[N_NODES * CH];
__device__ __align__(128) int2  g_rec[N_EDGES];       // (src, w_bits) grouped by dst
__device__ int g_hist[N_NODES];
__device__ int g_ptr[N_NODES + 1];
__device__ int g_cursor[N_NODES];
__device__ int g_bpub[SCAN_NB];                       // lookback publish words
__device__ int g_idx_is64;   // 1 if edge_index is int64, 0 if int32

// ---------------------------------------------------------------------------
// Kernel 0: zero histogram + lookback flags (all blocks); probe dtype (blk 0).
// int64 (nonneg < 2^31): every odd 32-bit word is zero.
// int32: odd words are random node ids -> some nonzero among 8192 w.p. ~1.
// ---------------------------------------------------------------------------
__global__ void k0_init(const int* __restrict__ ei32, int n_words) {
    int gid = blockIdx.x * blockDim.x + threadIdx.x;
    if (gid < N_NODES) g_hist[gid] = 0;
    if (gid < SCAN_NB) g_bpub[gid] = 0;

    if (blockIdx.x == 0) {
        __shared__ int any;
        if (threadIdx.x == 0) any = 0;
        __syncthreads();
        int limit = n_words < 8192 ? n_words : 8192;
        for (int i = 1 + 2 * threadIdx.x; i < limit; i += 2 * blockDim.x)
            if (ei32[i] != 0) any = 1;   // benign race: all writers store 1
        __syncthreads();
        if (threadIdx.x == 0) g_idx_is64 = (any == 0) ? 1 : 0;
    }
}

// ---------------------------------------------------------------------------
// Kernel 1: h = x @ w_gcn. FOUR nodes per warp: each w_t LDS value feeds
// 4 FFMAs. Fused: dst histogram (REDs hide under the DRAM-bound x read).
// ---------------------------------------------------------------------------
__global__ void k1_xw_hist(const float* __restrict__ x,
                           const float* __restrict__ w_gcn,
                           const int* __restrict__ ei32, int E) {
    __shared__ float w_t[F_IN * CH];    // [c][k], pitch 256: lane-consecutive
    const int tid = threadIdx.x;
    for (int i = tid; i < F_IN * CH; i += blockDim.x) {
        int k = i >> 4;
        int c = i & 15;
        w_t[c * F_IN + k] = w_gcn[i];
    }
    __syncthreads();

    const int gtid = blockIdx.x * blockDim.x + tid;
    const int nthreads = gridDim.x * blockDim.x;

    const int is64 = g_idx_is64;
    for (int e = gtid; e < E; e += nthreads) {
        int dst = is64 ? ei32[(size_t)2 * (E + e)] : ei32[(size_t)E + e];
        atomicAdd(&g_hist[dst], 1);   // no return -> RED
    }

    const int warp = gtid >> 5;
    const int lane = tid & 31;
    const int n0 = warp * 4;
    if (n0 >= N_NODES) return;       // N_NODES % 4 == 0

    const float* __restrict__ xr = x + (size_t)n0 * F_IN;
    float acc0[CH], acc1[CH], acc2[CH], acc3[CH];
#pragma unroll
    for (int c = 0; c < CH; c++) { acc0[c] = acc1[c] = acc2[c] = acc3[c] = 0.f; }

#pragma unroll
    for (int i = 0; i < F_IN / 32; i++) {
        int k = i * 32 + lane;
        float xa = xr[k];
        float xb = xr[F_IN + k];
        float xc = xr[2 * F_IN + k];
        float xd = xr[3 * F_IN + k];
#pragma unroll
        for (int c = 0; c < CH; c++) {
            float wv = w_t[c * F_IN + k];    // 1 LDS feeds 4 FFMA
            acc0[c] += xa * wv;
            acc1[c] += xb * wv;
            acc2[c] += xc * wv;
            acc3[c] += xd * wv;
        }
    }

#pragma unroll
    for (int m = 0; m < 4; m++) {
        float* acc = (m == 0) ? acc0 : (m == 1) ? acc1 : (m == 2) ? acc2 : acc3;
        float mine = 0.0f;
#pragma unroll
        for (int c = 0; c < CH; c++) {
            float v = acc[c];
#pragma unroll
            for (int o = 16; o > 0; o >>= 1)
                v += __shfl_xor_sync(0xFFFFFFFFu, v, o);
            if (lane == c) mine = v;
        }
        if (lane < CH) g_h[(size_t)(n0 + m) * CH + lane] = mine;
    }
}

// ---------------------------------------------------------------------------
// Kernel 2: single-pass scan (decoupled lookback). 98 blocks, all resident
// simultaneously (98 < 148 SMs) so publish-then-spin cannot deadlock.
// Each block: local Hillis-Steele scan, publish total (value|READY in ONE
// word -> no fence needed), spin-collect predecessor totals, write
// g_ptr/g_cursor with global offsets.
// ---------------------------------------------------------------------------
__global__ void k_scan() {
    __shared__ int s[SCAN_B];
    __shared__ int s_off;
    const int t = threadIdx.x;
    const int b = blockIdx.x;
    const int idx = b * SCAN_B + t;

    int v = (idx < N_NODES) ? g_hist[idx] : 0;
    s[t] = v;
    __syncthreads();
#pragma unroll
    for (int off = 1; off < SCAN_B; off <<= 1) {
        int u = (t >= off) ? s[t - off] : 0;
        __syncthreads();
        s[t] += u;
        __syncthreads();
    }

    if (t == 0) {
        s_off = 0;
        atomicExch(&g_bpub[b], s[SCAN_B - 1] | READY_BIT);   // publish own total
    }
    __syncthreads();

    // Lookback: thread t (< b) collects block t's total.
    if (t < b) {
        int u;
        do { u = atomicAdd(&g_bpub[t], 0); } while (!(u & READY_BIT));
        atomicAdd(&s_off, u & ~READY_BIT);
    }
    __syncthreads();

    int p = s[t] - v + s_off;            // global exclusive prefix
    if (idx < N_NODES) {
        g_ptr[idx] = p;
        g_cursor[idx] = p;
    }
    if (b == SCAN_NB - 1 && t == SCAN_B - 1)
        g_ptr[N_NODES] = s[t] + s_off;   // == E
}

// ---------------------------------------------------------------------------
// Kernel 3: scatter edges into dst-grouped record array.
// ---------------------------------------------------------------------------
__global__ void k2c_scatter(const int* __restrict__ ei32,
                            const float* __restrict__ ew, int E) {
    int e = blockIdx.x * blockDim.x + threadIdx.x;
    if (e >= E) return;

    int src, dst;
    if (g_idx_is64) {
        src = ei32[(size_t)2 * e];
        dst = ei32[(size_t)2 * (E + e)];
    } else {
        src = ei32[e];
        dst = ei32[(size_t)E + e];
    }
    float w = ew[e];

    int p = atomicAdd(&g_cursor[dst], 1);
    g_rec[p] = make_int2(src, __float_as_int(w));
}

// ---------------------------------------------------------------------------
// Kernel 4: atomic-free aggregation FUSED with FCN head. One warp per node.
// SHFL-FREE edge loop: lane group g (4 lanes, slot = lane>>2) loads record
// g_rec[base + g*8 + slot] directly -- 4 lanes same address = HW broadcast
// inside one LDG, no cross-lane dependency. 4 unrolled groups = 4 independent
// record->gather chains in flight (high MLP). Butterfly over slots; head
// computed warp-parallel (lane l does FCN units l and l+32).
// ---------------------------------------------------------------------------
__global__ void k2d_agg_head(const float* __restrict__ w0, const float* __restrict__ b0,
                             const float* __restrict__ w1, const float* __restrict__ b1,
                             float* __restrict__ out) {
    __shared__ float s_w0[CH * FCN];    // [c][f]: lane-consecutive reads
    __shared__ float s_w1[FCN];
    __shared__ float s_b0[FCN];
    __shared__ float s_b1;
    const int tid = threadIdx.x;
    for (int i = tid; i < CH * FCN; i += blockDim.x) s_w0[i] = w0[i];
    for (int i = tid; i < FCN; i += blockDim.x) { s_w1[i] = w1[i]; s_b0[i] = b0[i]; }
    if (tid == 0) s_b1 = b1[0];
    __syncthreads();

    const unsigned FULL = 0xFFFFFFFFu;
    int gtid = blockIdx.x * blockDim.x + tid;
    int n = gtid >> 5;
    if (n >= N_NODES) return;
    int lane = tid & 31;
    int slot = lane >> 2;     // 0..7 : edge slot within a group of 8
    int j = lane & 3;         // 0..3 : which float4 of the 16-ch row

    int start = g_ptr[n];
    int end = g_ptr[n + 1];

    float ax = 0.f, ay = 0.f, az = 0.f, aw = 0.f;

    for (int base = start; base < end; base += 32) {
#pragma unroll
        for (int g = 0; g < 4; g++) {
            int idx = base + g * 8 + slot;
            if (idx < end) {
                int2 r = g_rec[idx];                   // 4 lanes same addr: bcast
                float w = __int_as_float(r.y);
                const float4 hv = *(const float4*)(g_h + (size_t)r.x * CH + j * 4);
                ax += hv.x * w; ay += hv.y * w; az += hv.z * w; aw += hv.w * w;
            }
        }
    }

    // Reduce across the 8 edge-slots (lane bits 2..4): lanes 0-3 hold result
#pragma unroll
    for (int m = 4; m <= 16; m <<= 1) {
        ax += __shfl_xor_sync(FULL, ax, m);
        ay += __shfl_xor_sync(FULL, ay, m);
        az += __shfl_xor_sync(FULL, az, m);
        aw += __shfl_xor_sync(FULL, aw, m);
    }

    // Broadcast the 16 channels (relu'd) to all lanes: a[c], c = 4q+{0..3}
    float a[CH];
#pragma unroll
    for (int q = 0; q < 4; q++) {
        a[4 * q + 0] = fmaxf(__shfl_sync(FULL, ax, q), 0.f);
        a[4 * q + 1] = fmaxf(__shfl_sync(FULL, ay, q), 0.f);
        a[4 * q + 2] = fmaxf(__shfl_sync(FULL, az, q), 0.f);
        a[4 * q + 3] = fmaxf(__shfl_sync(FULL, aw, q), 0.f);
    }

    // FCN head: lane l computes units f=l and f=l+32.
    float o1a = s_b0[lane];
    float o1b = s_b0[lane + 32];
#pragma unroll
    for (int c = 0; c < CH; c++) {
        o1a += a[c] * s_w0[c * FCN + lane];        // conflict-free LDS
        o1b += a[c] * s_w0[c * FCN + lane + 32];
    }
    o1a = fmaxf(o1a, 0.f);
    o1b = fmaxf(o1b, 0.f);
    float o2 = o1a * s_w1[lane] + o1b * s_w1[lane + 32];
#pragma unroll
    for (int m = 16; m > 0; m >>= 1)
        o2 += __shfl_xor_sync(FULL, o2, m);
    if (lane == 0) out[n] = o2 + s_b1;
}

// ---------------------------------------------------------------------------
// Launcher. Inputs identified by element count (robust to ordering):
//   x: 25,600,000   edge_index: 6,400,000   edge_w: 3,200,000
//   w_gcn: 4096     w0: 1024   b0: 64 (first)   w1: 64 (second)   b1: 1
// ---------------------------------------------------------------------------
extern "C" void kernel_launch(void* const* d_in, const int* in_sizes, int n_in,
                              void* d_out, int out_size) {
    const float* x = nullptr;
    const int* ei = nullptr;
    const float* ew = nullptr;
    const float* wg = nullptr;
    const float* w0 = nullptr;
    const float* b0 = nullptr;
    const float* w1 = nullptr;
    const float* b1 = nullptr;
    int E = 0;
    int seen64 = 0;

    for (int i = 0; i < n_in; i++) {
        int s = in_sizes[i];
        if (s == N_NODES * F_IN)      x  = (const float*)d_in[i];
        else if (s == 2 * N_EDGES)    { ei = (const int*)d_in[i]; E = s / 2; }
        else if (s == N_EDGES)        ew = (const float*)d_in[i];
        else if (s == F_IN * CH)      wg = (const float*)d_in[i];
        else if (s == CH * FCN)       w0 = (const float*)d_in[i];
        else if (s == FCN)            { if (seen64++ == 0) b0 = (const float*)d_in[i];
                                        else               w1 = (const float*)d_in[i]; }
        else if (s == 1)              b1 = (const float*)d_in[i];
    }

    float* out = (float*)d_out;

    // K0: zero hist + lookback flags + dtype probe
    k0_init<<<(N_NODES + 255) / 256, 256>>>(ei, 2 * E);

    // K1: 4 nodes per warp GEMV + fused dst histogram
    {
        int warps = N_NODES / 4;                 // 25000
        int threads = 256;
        int blocks = (warps * 32 + threads - 1) / threads;  // 3125
        k1_xw_hist<<<blocks, threads>>>(x, wg, ei, E);
    }

    // K2: single-pass lookback scan
    k_scan<<<SCAN_NB, SCAN_B>>>();

    // K3: scatter into CSR records
    k2c_scatter<<<(E + 255) / 256, 256>>>(ei, ew, E);

    // K4: atomic-free aggregation + FCN head, warp per node
    k2d_agg_head<<<(N_NODES * 32 + 255) / 256, 256>>>(w0, b0, w1, b1, out);
}

// round 8
// speedup vs baseline: 2.3220x; 1.1246x over previous
#include <cuda_runtime.h>
#include <cuda_bf16.h>
#include <cstdint>

#define N_NODES 100000
#define N_EDGES 3200000
#define F_IN 256
#define CH 16
#define FCN 64

#define SCAN_B 1024
#define SCAN_NB ((N_NODES + SCAN_B - 1) / SCAN_B)   // 98
#define READY_BIT 0x40000000

// Scratch: __device__ globals (no allocation allowed). Statically zeroed at
// load; kernels restore the zero state each call so graph replays see
// identical initial conditions (scan re-zeros hist; scatter resets bpub).
__device__ __align__(128) float g_h[N_NODES * CH];
__device__ __align__(128) int2  g_rec[N_EDGES];       // (src, w_bits) grouped by dst
__device__ int g_hist[N_NODES];                       // zero-init; re-zeroed in k_scan
__device__ int g_ptr[N_NODES + 1];
__device__ int g_cursor[N_NODES];
__device__ int g_bpub[SCAN_NB];                       // zero-init; reset in scatter
__device__ int g_idx_is64;                            // published by k1

// ---------------------------------------------------------------------------
// log-halving cross-lane reduction of 16 per-channel partials over 32 lanes.
// 16 shfls (8+4+2+1+1) instead of 16 butterflies (80 shfls).
// Returns the full sum of channel chan(lane) = bitrev4(lane&15); lanes l and
// l^16 hold the same channel.
// ---------------------------------------------------------------------------
__device__ __forceinline__ float reduce16(const float* r, int lane) {
    const unsigned FULL = 0xFFFFFFFFu;
    float t[8];
    bool hi = (lane & 1);
#pragma unroll
    for (int j = 0; j < 8; j++) {
        float give = hi ? r[j] : r[j + 8];
        float keep = hi ? r[j + 8] : r[j];
        t[j] = keep + __shfl_xor_sync(FULL, give, 1);
    }
    float u[4];
    hi = (lane & 2);
#pragma unroll
    for (int j = 0; j < 4; j++) {
        float give = hi ? t[j] : t[j + 4];
        float keep = hi ? t[j + 4] : t[j];
        u[j] = keep + __shfl_xor_sync(FULL, give, 2);
    }
    hi = (lane & 4);
    float g0 = hi ? u[0] : u[2];
    float k0 = hi ? u[2] : u[0];
    float v0 = k0 + __shfl_xor_sync(FULL, g0, 4);
    float g1 = hi ? u[1] : u[3];
    float k1 = hi ? u[3] : u[1];
    float v1 = k1 + __shfl_xor_sync(FULL, g1, 4);

    hi = (lane & 8);
    float g2 = hi ? v0 : v1;
    float k2 = hi ? v1 : v0;
    float w = k2 + __shfl_xor_sync(FULL, g2, 8);

    w += __shfl_xor_sync(FULL, w, 16);
    return w;
}

__device__ __forceinline__ int chan_of_lane(int lane) {
    return ((lane & 1) << 3) | ((lane & 2) << 1) | ((lane & 4) >> 1) | ((lane & 8) >> 3);
}

// ---------------------------------------------------------------------------
// Kernel 1: h = x @ w_gcn (4 nodes/warp, float4 loads, LDS.128 weights)
// + per-warp dtype probe (ballot over first 64 odd words)
// + fused dst histogram (REDs hide under the DRAM-bound 102MB x read).
// ---------------------------------------------------------------------------
__global__ void k1_xw_hist(const float* __restrict__ x,
                           const float* __restrict__ w_gcn,
                           const int* __restrict__ ei32, int E) {
    const unsigned FULL = 0xFFFFFFFFu;
    __shared__ __align__(16) float w_t[F_IN * CH];   // [c][k], pitch 256
    const int tid = threadIdx.x;
    for (int i = tid; i < F_IN * CH; i += blockDim.x) {
        int k = i >> 4;
        int c = i & 15;
        w_t[c * F_IN + k] = w_gcn[i];
    }
    __syncthreads();

    const int gtid = blockIdx.x * blockDim.x + tid;
    const int nthreads = gridDim.x * blockDim.x;
    const int lane = tid & 31;

    // Per-warp dtype probe: odd words 1..63 are 0 iff int64 layout.
    int oddw = ei32[2 * lane + 1];
    unsigned nz = __ballot_sync(FULL, oddw != 0);
    const bool is64 = (nz == 0);
    if (gtid == 0) g_idx_is64 = is64 ? 1 : 0;   // for scan-independent kernels

    // Histogram of destinations
    for (int e = gtid; e < E; e += nthreads) {
        int dst = is64 ? ei32[(size_t)2 * (E + e)] : ei32[(size_t)E + e];
        atomicAdd(&g_hist[dst], 1);   // no return -> RED
    }

    const int warp = gtid >> 5;
    const int n0 = warp * 4;
    if (n0 >= N_NODES) return;       // N_NODES % 4 == 0

    const float4* __restrict__ xr4 = (const float4*)(x + (size_t)n0 * F_IN);
    const float4* wt4 = (const float4*)w_t;          // [c][k4], pitch 64

    float acc0[CH], acc1[CH], acc2[CH], acc3[CH];
#pragma unroll
    for (int c = 0; c < CH; c++) { acc0[c] = acc1[c] = acc2[c] = acc3[c] = 0.f; }

#pragma unroll
    for (int i = 0; i < 2; i++) {
        int k4 = i * 32 + lane;                      // float4 column index
        float4 xa = xr4[k4];                         // LDG.128, coalesced
        float4 xb = xr4[64 + k4];
        float4 xc = xr4[128 + k4];
        float4 xd = xr4[192 + k4];
#pragma unroll
        for (int c = 0; c < CH; c++) {
            float4 wv = wt4[c * 64 + k4];            // LDS.128, conflict-free
            acc0[c] += xa.x * wv.x + xa.y * wv.y + xa.z * wv.z + xa.w * wv.w;
            acc1[c] += xb.x * wv.x + xb.y * wv.y + xb.z * wv.z + xb.w * wv.w;
            acc2[c] += xc.x * wv.x + xc.y * wv.y + xc.z * wv.z + xc.w * wv.w;
            acc3[c] += xd.x * wv.x + xd.y * wv.y + xd.z * wv.z + xd.w * wv.w;
        }
    }

    const int chan = chan_of_lane(lane);
    float s0 = reduce16(acc0, lane);
    float s1 = reduce16(acc1, lane);
    float s2 = reduce16(acc2, lane);
    float s3 = reduce16(acc3, lane);
    if (lane < 16) {
        g_h[(size_t)(n0 + 0) * CH + chan] = s0;
        g_h[(size_t)(n0 + 1) * CH + chan] = s1;
        g_h[(size_t)(n0 + 2) * CH + chan] = s2;
        g_h[(size_t)(n0 + 3) * CH + chan] = s3;
    }
}

// ---------------------------------------------------------------------------
// Kernel 2: single-pass scan (decoupled lookback). 98 blocks all resident
// (98 < 148 SMs) -> publish-then-spin cannot deadlock. Re-zeros g_hist after
// reading so the next graph replay starts clean.
// ---------------------------------------------------------------------------
__global__ void k_scan() {
    __shared__ int s[SCAN_B];
    __shared__ int s_off;
    const int t = threadIdx.x;
    const int b = blockIdx.x;
    const int idx = b * SCAN_B + t;

    int v = 0;
    if (idx < N_NODES) {
        v = g_hist[idx];
        g_hist[idx] = 0;                 // restore zero state for next call
    }
    s[t] = v;
    __syncthreads();
#pragma unroll
    for (int off = 1; off < SCAN_B; off <<= 1) {
        int u = (t >= off) ? s[t - off] : 0;
        __syncthreads();
        s[t] += u;
        __syncthreads();
    }

    if (t == 0) {
        s_off = 0;
        atomicExch(&g_bpub[b], s[SCAN_B - 1] | READY_BIT);   // publish own total
    }
    __syncthreads();

    if (t < b) {
        int u;
        do { u = atomicAdd(&g_bpub[t], 0); } while (!(u & READY_BIT));
        atomicAdd(&s_off, u & ~READY_BIT);
    }
    __syncthreads();

    int p = s[t] - v + s_off;            // global exclusive prefix
    if (idx < N_NODES) {
        g_ptr[idx] = p;
        g_cursor[idx] = p;
    }
    if (b == SCAN_NB - 1 && t == SCAN_B - 1)
        g_ptr[N_NODES] = s[t] + s_off;   // == E
}

// ---------------------------------------------------------------------------
// Kernel 3: scatter edges into dst-grouped record array. Also resets the
// lookback publish flags (scan has completed; stream order guarantees it).
// ---------------------------------------------------------------------------
__global__ void k2c_scatter(const int* __restrict__ ei32,
                            const float* __restrict__ ew, int E) {
    if (blockIdx.x == 0 && threadIdx.x < SCAN_NB) g_bpub[threadIdx.x] = 0;

    int e = blockIdx.x * blockDim.x + threadIdx.x;
    if (e >= E) return;

    int src, dst;
    if (g_idx_is64) {
        src = ei32[(size_t)2 * e];
        dst = ei32[(size_t)2 * (E + e)];
    } else {
        src = ei32[e];
        dst = ei32[(size_t)E + e];
    }
    float w = ew[e];

    int p = atomicAdd(&g_cursor[dst], 1);
    g_rec[p] = make_int2(src, __float_as_int(w));
}

// ---------------------------------------------------------------------------
// Kernel 4: atomic-free aggregation FUSED with FCN head. One warp per node.
// Lane group g (4 lanes, slot = lane>>2) loads its record directly (4 lanes
// same address = HW broadcast within one LDG); gathers 64B h-row coalesced.
// Butterfly over slots; head computed warp-parallel.
// ---------------------------------------------------------------------------
__global__ void k2d_agg_head(const float* __restrict__ w0, const float* __restrict__ b0,
                             const float* __restrict__ w1, const float* __restrict__ b1,
                             float* __restrict__ out) {
    __shared__ float s_w0[CH * FCN];    // [c][f]: lane-consecutive reads
    __shared__ float s_w1[FCN];
    __shared__ float s_b0[FCN];
    __shared__ float s_b1;
    const int tid = threadIdx.x;
    for (int i = tid; i < CH * FCN; i += blockDim.x) s_w0[i] = w0[i];
    for (int i = tid; i < FCN; i += blockDim.x) { s_w1[i] = w1[i]; s_b0[i] = b0[i]; }
    if (tid == 0) s_b1 = b1[0];
    __syncthreads();

    const unsigned FULL = 0xFFFFFFFFu;
    int gtid = blockIdx.x * blockDim.x + tid;
    int n = gtid >> 5;
    if (n >= N_NODES) return;
    int lane = tid & 31;
    int slot = lane >> 2;     // 0..7 : edge slot within a group of 8
    int j = lane & 3;         // 0..3 : which float4 of the 16-ch row

    int start = g_ptr[n];
    int end = g_ptr[n + 1];

    float ax = 0.f, ay = 0.f, az = 0.f, aw = 0.f;

    for (int base = start; base < end; base += 32) {
#pragma unroll
        for (int g = 0; g < 4; g++) {
            int idx = base + g * 8 + slot;
            if (idx < end) {
                int2 r = g_rec[idx];                   // 4 lanes same addr: bcast
                float w = __int_as_float(r.y);
                const float4 hv = *(const float4*)(g_h + (size_t)r.x * CH + j * 4);
                ax += hv.x * w; ay += hv.y * w; az += hv.z * w; aw += hv.w * w;
            }
        }
    }

    // Reduce across the 8 edge-slots: lanes 0-3 hold the 16 channels
#pragma unroll
    for (int m = 4; m <= 16; m <<= 1) {
        ax += __shfl_xor_sync(FULL, ax, m);
        ay += __shfl_xor_sync(FULL, ay, m);
        az += __shfl_xor_sync(FULL, az, m);
        aw += __shfl_xor_sync(FULL, aw, m);
    }

    // Broadcast the 16 channels (relu'd) to all lanes
    float a[CH];
#pragma unroll
    for (int q = 0; q < 4; q++) {
        a[4 * q + 0] = fmaxf(__shfl_sync(FULL, ax, q), 0.f);
        a[4 * q + 1] = fmaxf(__shfl_sync(FULL, ay, q), 0.f);
        a[4 * q + 2] = fmaxf(__shfl_sync(FULL, az, q), 0.f);
        a[4 * q + 3] = fmaxf(__shfl_sync(FULL, aw, q), 0.f);
    }

    // FCN head: lane l computes units f=l and f=l+32.
    float o1a = s_b0[lane];
    float o1b = s_b0[lane + 32];
#pragma unroll
    for (int c = 0; c < CH; c++) {
        o1a += a[c] * s_w0[c * FCN + lane];        // conflict-free LDS
        o1b += a[c] * s_w0[c * FCN + lane + 32];
    }
    o1a = fmaxf(o1a, 0.f);
    o1b = fmaxf(o1b, 0.f);
    float o2 = o1a * s_w1[lane] + o1b * s_w1[lane + 32];
#pragma unroll
    for (int m = 16; m > 0; m >>= 1)
        o2 += __shfl_xor_sync(FULL, o2, m);
    if (lane == 0) out[n] = o2 + s_b1;
}

// ---------------------------------------------------------------------------
// Launcher. Inputs identified by element count (robust to ordering):
//   x: 25,600,000   edge_index: 6,400,000   edge_w: 3,200,000
//   w_gcn: 4096     w0: 1024   b0: 64 (first)   w1: 64 (second)   b1: 1
// ---------------------------------------------------------------------------
extern "C" void kernel_launch(void* const* d_in, const int* in_sizes, int n_in,
                              void* d_out, int out_size) {
    const float* x = nullptr;
    const int* ei = nullptr;
    const float* ew = nullptr;
    const float* wg = nullptr;
    const float* w0 = nullptr;
    const float* b0 = nullptr;
    const float* w1 = nullptr;
    const float* b1 = nullptr;
    int E = 0;
    int seen64 = 0;

    for (int i = 0; i < n_in; i++) {
        int s = in_sizes[i];
        if (s == N_NODES * F_IN)      x  = (const float*)d_in[i];
        else if (s == 2 * N_EDGES)    { ei = (const int*)d_in[i]; E = s / 2; }
        else if (s == N_EDGES)        ew = (const float*)d_in[i];
        else if (s == F_IN * CH)      wg = (const float*)d_in[i];
        else if (s == CH * FCN)       w0 = (const float*)d_in[i];
        else if (s == FCN)            { if (seen64++ == 0) b0 = (const float*)d_in[i];
                                        else               w1 = (const float*)d_in[i]; }
        else if (s == 1)              b1 = (const float*)d_in[i];
    }

    float* out = (float*)d_out;

    // Launch 1: GEMV (4 nodes/warp) + dtype probe + fused dst histogram
    {
        int warps = N_NODES / 4;                 // 25000
        int threads = 256;
        int blocks = (warps * 32 + threads - 1) / threads;  // 3125
        k1_xw_hist<<<blocks, threads>>>(x, wg, ei, E);
    }

    // Launch 2: single-pass lookback scan (+ hist re-zero)
    k_scan<<<SCAN_NB, SCAN_B>>>();

    // Launch 3: scatter into CSR records (+ bpub reset)
    k2c_scatter<<<(E + 255) / 256, 256>>>(ei, ew, E);

    // Launch 4: atomic-free aggregation + FCN head, warp per node  [profiled]
    k2d_agg_head<<<(N_NODES * 32 + 255) / 256, 256>>>(w0, b0, w1, b1, out);
}